// round 5
// baseline (speedup 1.0000x reference)
#include <cuda_runtime.h>
#include <math.h>

// Problem constants (hardcoded in reference)
#define B 32
#define D 128
#define K 512
#define C 10
#define R (B + C)          // 42 factor rows (32 x-rows then 10 mu-rows)
#define NCTA 64
#define CHUNK (K / NCTA)   // 8 k-columns per CTA
#define NT 1024

// Per-CTA partial h [NCTA][B*C] and completion counter
__device__ float g_hpart[NCTA * B * C];
__device__ int   g_cnt = 0;

__global__ __launch_bounds__(NT, 1) void fused_kernel(
    const float* __restrict__ x,
    const float* __restrict__ mu,
    const float* __restrict__ U,
    const float* __restrict__ V,
    float* __restrict__ out) {
    // src transposed: src_sT[d][r], padded row 44 (even -> float2 aligned)
    __shared__ float src_sT[D * 44];
    __shared__ float W_s[2][D][CHUNK];      // U chunk, V chunk
    __shared__ float part[4][R][CHUNK];     // d-split partials
    __shared__ float fac_s[R * CHUNK];      // combined factor chunk
    __shared__ float hfin[B * C];           // finale scratch
    __shared__ int   sflag;

    const int t  = threadIdx.x;
    const int k0 = blockIdx.x * CHUNK;

    // ---- phase 0: cooperative loads (one MLP-batched DRAM exposure) ----
    // src rows (x then mu), transposed into smem
    for (int idx = t; idx < R * D; idx += NT) {
        const int r = idx >> 7;          // row 0..41
        const int d = idx & (D - 1);
        const float v = (r < B) ? x[r * D + d] : mu[(r - B) * D + d];
        src_sT[d * 44 + r] = v;
    }
    // W chunks: 2 matrices x 128 rows x 2 float4
    if (t < 512) {
        const int w  = t >> 8;           // 0=U, 1=V
        const int d  = (t >> 1) & (D - 1);
        const int c4 = t & 1;
        const float* Wp = w ? V : U;
        float4 v = reinterpret_cast<const float4*>(Wp + d * K + k0)[c4];
        reinterpret_cast<float4*>(&W_s[w][d][c4 * 4])[0] = v;
    }
    __syncthreads();

    // ---- phase 1: factor chunk, 21 row-pairs x 2 kc-float4 x 4 d-splits ----
    if (t < 168) {
        const int kcg = t & 1;           // which float4 of the 8 cols
        const int q   = t >> 1;          // 0..83
        const int ds  = q / 21;          // d-split 0..3
        const int rg  = q - ds * 21;     // row pair 0..20
        const int w   = (rg >= 16);      // rows >=32 use V
        const int r0  = rg * 2;

        float4 a0 = make_float4(0.f, 0.f, 0.f, 0.f);
        float4 a1 = make_float4(0.f, 0.f, 0.f, 0.f);
        const int dbase = ds * 32;
#pragma unroll
        for (int d = 0; d < 32; d++) {
            const int dd = dbase + d;
            float2 s  = *reinterpret_cast<const float2*>(&src_sT[dd * 44 + r0]);
            float4 wv = *reinterpret_cast<const float4*>(&W_s[w][dd][kcg * 4]);
            a0.x = fmaf(s.x, wv.x, a0.x); a0.y = fmaf(s.x, wv.y, a0.y);
            a0.z = fmaf(s.x, wv.z, a0.z); a0.w = fmaf(s.x, wv.w, a0.w);
            a1.x = fmaf(s.y, wv.x, a1.x); a1.y = fmaf(s.y, wv.y, a1.y);
            a1.z = fmaf(s.y, wv.z, a1.z); a1.w = fmaf(s.y, wv.w, a1.w);
        }
        reinterpret_cast<float4*>(&part[ds][r0][kcg * 4])[0]     = a0;
        reinterpret_cast<float4*>(&part[ds][r0 + 1][kcg * 4])[0] = a1;
    }
    __syncthreads();

    // ---- phase 2: combine the 4 d-split partials ----
    if (t < R * CHUNK) {
        const int r  = t >> 3;
        const int kc = t & 7;
        fac_s[t] = part[0][r][kc] + part[1][r][kc] + part[2][r][kc] + part[3][r][kc];
    }
    __syncthreads();

    // ---- phase 3: partial h[b][c] over this chunk ----
    if (t < B * C) {
        const int b = t / C;
        const int c = t - b * C;
        const float* f1 = fac_s + b * CHUNK;
        const float* f2 = fac_s + (B + c) * CHUNK;
        float h = 0.f;
#pragma unroll
        for (int kc = 0; kc < CHUNK; kc++) h = fmaf(f1[kc], f2[kc], h);
        g_hpart[blockIdx.x * (B * C) + t] = h;
    }

    // ---- completion: last-arriving CTA does the finale (no polling) ----
    __threadfence();
    __syncthreads();
    if (t == 0) {
        const int old = atomicAdd(&g_cnt, 1);
        sflag = (old == NCTA - 1);
    }
    __syncthreads();
    if (!sflag) return;

    __threadfence();   // acquire: order hpart reads after observing all arrivals
    if (t < B * C) {
        float s0 = 0.f, s1 = 0.f, s2 = 0.f, s3 = 0.f;
#pragma unroll
        for (int j = 0; j < NCTA; j += 4) {
            s0 += g_hpart[(j + 0) * (B * C) + t];
            s1 += g_hpart[(j + 1) * (B * C) + t];
            s2 += g_hpart[(j + 2) * (B * C) + t];
            s3 += g_hpart[(j + 3) * (B * C) + t];
        }
        hfin[t] = (s0 + s1) + (s2 + s3);
    }
    __syncthreads();

    if (t < B) {
        float h[C];
        float m = -INFINITY;
#pragma unroll
        for (int c = 0; c < C; c++) { h[c] = hfin[t * C + c]; m = fmaxf(m, h[c]); }
        float se = 0.f;
#pragma unroll
        for (int c = 0; c < C; c++) se += expf(h[c] - m);
        const float lse = m + logf(se);
#pragma unroll
        for (int c = 0; c < C; c++) out[t * C + c] = h[c] - lse;
    }
    if (t == 0) g_cnt = 0;   // reset for next graph replay
}

extern "C" void kernel_launch(void* const* d_in, const int* in_sizes, int n_in,
                              void* d_out, int out_size) {
    const float* x  = (const float*)d_in[0];  // [32, 128]
    const float* mu = (const float*)d_in[1];  // [10, 128]
    const float* U  = (const float*)d_in[2];  // [128, 512]
    const float* V  = (const float*)d_in[3];  // [128, 512]
    float* out = (float*)d_out;               // [32, 10]

    fused_kernel<<<NCTA, NT>>>(x, mu, U, V, out);
}